// round 1
// baseline (speedup 1.0000x reference)
#include <cuda_runtime.h>
#include <math.h>

#define DD  128
#define HW  16384            // 128*128
#define VOL 2097152          // 128^3

// ---- scratch (static device globals: allocation-free at launch time) ----
__device__ float  g_tmp3[3 * VOL];   // 24 MB: intermediate 3-ch warped field
__device__ float  g_WA[VOL];         // 8 MB : warp(image_A, phi_AB)
__device__ float  g_WB[VOL];         // 8 MB : warp(image_B, phi_BA)
__device__ float  g_b5a[5 * VOL];    // 40 MB: blur ping
__device__ float  g_b5b[5 * VOL];    // 40 MB: blur pong
__device__ double g_acc[16];         // reductions

// gaussian kernel, sigma=1, ksize=5 (normalized exp(-0.5 x^2), x=-2..2)
__constant__ float c_gk[5] = {
    0.05448868454964294f, 0.24420134200323332f, 0.40261995089424437f,
    0.24420134200323332f, 0.05448868454964294f };

__device__ __forceinline__ float idgv(int v) { return -1.0f + (float)v * (2.0f / 127.0f); }

__device__ __forceinline__ void get_coords(const float* __restrict__ phi, int i,
                                           float& z, float& y, float& x) {
    z = (phi[i]           + 1.0f) * 0.5f * 127.0f;
    y = (phi[VOL + i]     + 1.0f) * 0.5f * 127.0f;
    x = (phi[2 * VOL + i] + 1.0f) * 0.5f * 127.0f;
}

// visit the (up to) 8 valid trilinear corners with their weights
template <typename F>
__device__ __forceinline__ void tri_accum(float z, float y, float x, F f) {
    float zf = floorf(z), yf = floorf(y), xf = floorf(x);
    int z0 = (int)zf, y0 = (int)yf, x0 = (int)xf;
    float fz = z - zf, fy = y - yf, fx = x - xf;
    float wz0 = 1.0f - fz, wy0 = 1.0f - fy, wx0 = 1.0f - fx;
#pragma unroll
    for (int dz = 0; dz < 2; dz++) {
        int zi = z0 + dz;
        if (zi < 0 || zi >= DD) continue;
        float wz = dz ? fz : wz0;
#pragma unroll
        for (int dy = 0; dy < 2; dy++) {
            int yi = y0 + dy;
            if (yi < 0 || yi >= DD) continue;
            float wzy = wz * (dy ? fy : wy0);
#pragma unroll
            for (int dx = 0; dx < 2; dx++) {
                int xi = x0 + dx;
                if (xi < 0 || xi >= DD) continue;
                float w = wzy * (dx ? fx : wx0);
                f(zi, yi, xi, w);
            }
        }
    }
}

// 256-thread block reduction -> one atomicAdd(double)
__device__ __forceinline__ void block_add(double v, double* dst) {
    __shared__ double sm[8];
    int lane = threadIdx.x & 31;
    int wid  = threadIdx.x >> 5;
#pragma unroll
    for (int o = 16; o > 0; o >>= 1) v += __shfl_down_sync(0xffffffffu, v, o);
    __syncthreads();
    if (lane == 0) sm[wid] = v;
    __syncthreads();
    if (wid == 0) {
        double t = (lane < 8) ? sm[lane] : 0.0;
#pragma unroll
        for (int o = 4; o > 0; o >>= 1) t += __shfl_down_sync(0xffffffffu, t, o);
        if (lane == 0) atomicAdd(dst, t);
    }
}

__global__ void k_init() {
    if (threadIdx.x < 16) g_acc[threadIdx.x] = 0.0;
}

// g_tmp3 = warp(Ieps, phi); Ieps gathered analytically (idg + noise/128)
__global__ void k_warp_ieps(const float* __restrict__ phi, const float* __restrict__ noise) {
    int i = blockIdx.x * 256 + threadIdx.x;
    float z, y, x;
    get_coords(phi, i, z, y, x);
    float o0 = 0.f, o1 = 0.f, o2 = 0.f;
    tri_accum(z, y, x, [&](int zi, int yi, int xi, float w) {
        int idx = (zi * DD + yi) * DD + xi;
        o0 += w * (idgv(zi) + noise[idx]           * (1.0f / 128.0f));
        o1 += w * (idgv(yi) + noise[VOL + idx]     * (1.0f / 128.0f));
        o2 += w * (idgv(xi) + noise[2 * VOL + idx] * (1.0f / 128.0f));
    });
    g_tmp3[i] = o0; g_tmp3[VOL + i] = o1; g_tmp3[2 * VOL + i] = o2;
}

// acc[0] += sum( (Ieps - warp(g_tmp3, phi))^2 )  over 3 channels
__global__ void k_warp3_mse(const float* __restrict__ phi, const float* __restrict__ noise) {
    int i = blockIdx.x * 256 + threadIdx.x;
    float z, y, x;
    get_coords(phi, i, z, y, x);
    float o0 = 0.f, o1 = 0.f, o2 = 0.f;
    tri_accum(z, y, x, [&](int zi, int yi, int xi, float w) {
        int idx = (zi * DD + yi) * DD + xi;
        o0 += w * g_tmp3[idx];
        o1 += w * g_tmp3[VOL + idx];
        o2 += w * g_tmp3[2 * VOL + idx];
    });
    int zz = i >> 14, yy = (i >> 7) & 127, xx = i & 127;
    float e0 = idgv(zz) + noise[i]           * (1.0f / 128.0f);
    float e1 = idgv(yy) + noise[VOL + i]     * (1.0f / 128.0f);
    float e2 = idgv(xx) + noise[2 * VOL + i] * (1.0f / 128.0f);
    float d0 = e0 - o0, d1 = e1 - o1, d2 = e2 - o2;
    block_add((double)(d0 * d0) + (double)(d1 * d1) + (double)(d2 * d2), &g_acc[0]);
}

// dst = warp(src, phi), 1 channel
__global__ void k_warp1(const float* __restrict__ phi, const float* __restrict__ src,
                        float* __restrict__ dst) {
    int i = blockIdx.x * 256 + threadIdx.x;
    float z, y, x;
    get_coords(phi, i, z, y, x);
    float o = 0.f;
    tri_accum(z, y, x, [&](int zi, int yi, int xi, float w) {
        o += w * src[(zi * DD + yi) * DD + xi];
    });
    dst[i] = o;
}

// dice partial sums: acc[b]=sum(wl*other), acc[b+1]=sum(wl), acc[b+2]=sum(other)
__global__ void k_warp1_dice(const float* __restrict__ phi, const float* __restrict__ src,
                             const float* __restrict__ other, int accbase) {
    int i = blockIdx.x * 256 + threadIdx.x;
    float z, y, x;
    get_coords(phi, i, z, y, x);
    float wl = 0.f;
    tri_accum(z, y, x, [&](int zi, int yi, int xi, float w) {
        wl += w * src[(zi * DD + yi) * DD + xi];
    });
    float ov = other[i];
    block_add((double)(wl * ov), &g_acc[accbase]);
    block_add((double)wl,        &g_acc[accbase + 1]);
    block_add((double)ov,        &g_acc[accbase + 2]);
}

// z-axis blur of {I, J, I*J, I*I, J*J} -> g_b5a
__global__ void k_blurZ(const float* __restrict__ A, const float* __restrict__ B) {
    int i = blockIdx.x * 256 + threadIdx.x;
    int z = i >> 14;
    float bI = 0.f, bJ = 0.f, bIJ = 0.f, bII = 0.f, bJJ = 0.f;
#pragma unroll
    for (int t = 0; t < 5; t++) {
        int zz = z + t - 2;
        if ((unsigned)zz < (unsigned)DD) {
            float a = A[i + (t - 2) * HW];
            float b = B[i + (t - 2) * HW];
            float k = c_gk[t];
            bI += k * a; bJ += k * b;
            bIJ += k * a * b; bII += k * a * a; bJJ += k * b * b;
        }
    }
    g_b5a[i] = bI; g_b5a[VOL + i] = bJ; g_b5a[2 * VOL + i] = bIJ;
    g_b5a[3 * VOL + i] = bII; g_b5a[4 * VOL + i] = bJJ;
}

// y-axis blur: g_b5a -> g_b5b (5 channels)
__global__ void k_blurY() {
    int i = blockIdx.x * 256 + threadIdx.x;
    int y = (i >> 7) & 127;
    float v[5] = {0.f, 0.f, 0.f, 0.f, 0.f};
#pragma unroll
    for (int t = 0; t < 5; t++) {
        int yy = y + t - 2;
        if ((unsigned)yy < (unsigned)DD) {
            float k = c_gk[t];
            int off = i + (t - 2) * DD;
#pragma unroll
            for (int c = 0; c < 5; c++) v[c] += k * g_b5b[0 * VOL] * 0.f, v[c] = v[c]; // placeholder removed below
        }
    }
    // (rewritten without the placeholder)
#pragma unroll
    for (int c = 0; c < 5; c++) v[c] = 0.f;
#pragma unroll
    for (int t = 0; t < 5; t++) {
        int yy = y + t - 2;
        if ((unsigned)yy < (unsigned)DD) {
            float k = c_gk[t];
            int off = i + (t - 2) * DD;
#pragma unroll
            for (int c = 0; c < 5; c++) v[c] += k * g_b5a[c * VOL + off];
        }
    }
#pragma unroll
    for (int c = 0; c < 5; c++) g_b5b[c * VOL + i] = v[c];
}

// x-axis blur of g_b5b + fused LNCC reduction -> g_acc[accidx]
__global__ void k_blurX_red(int accidx) {
    int i = blockIdx.x * 256 + threadIdx.x;
    int x = i & 127;
    float v[5] = {0.f, 0.f, 0.f, 0.f, 0.f};
#pragma unroll
    for (int t = 0; t < 5; t++) {
        int xx = x + t - 2;
        if ((unsigned)xx < (unsigned)DD) {
            float k = c_gk[t];
            int off = i + (t - 2);
#pragma unroll
            for (int c = 0; c < 5; c++) v[c] += k * g_b5b[c * VOL + off];
        }
    }
    float bI = v[0], bJ = v[1], bIJ = v[2], bII = v[3], bJJ = v[4];
    float cross = bIJ - bI * bJ;
    float varI  = fmaxf(bII - bI * bI, 0.0f) + 1e-5f;
    float varJ  = fmaxf(bJJ - bJ * bJ, 0.0f) + 1e-5f;
    float val   = 1.0f - cross / sqrtf(varI * varJ);
    block_add((double)val, &g_acc[accidx]);
}

__global__ void k_final(float* __restrict__ out) {
    double ic    = g_acc[0] / (3.0 * (double)VOL);
    double dice1 = (2.0 * g_acc[1] + 1e-5) / (g_acc[2] + g_acc[3] + 1e-5);
    double dice2 = (2.0 * g_acc[4] + 1e-5) / (g_acc[5] + g_acc[6] + 1e-5);
    double dl    = (1.0 - dice1) + (1.0 - dice2);
    double sim   = (g_acc[7] + g_acc[8]) / (double)VOL;
    out[0] = (float)(128.0 * ic + sim + dl);
}

extern "C" void kernel_launch(void* const* d_in, const int* in_sizes, int n_in,
                              void* d_out, int out_size) {
    const float* phiAB = (const float*)d_in[0];
    const float* phiBA = (const float*)d_in[1];
    const float* imgA  = (const float*)d_in[2];
    const float* imgB  = (const float*)d_in[3];
    const float* labA  = (const float*)d_in[4];
    const float* labB  = (const float*)d_in[5];
    const float* noise = (const float*)d_in[6];
    float* out = (float*)d_out;

    float *pWA = nullptr, *pWB = nullptr;
    cudaGetSymbolAddress((void**)&pWA, g_WA);
    cudaGetSymbolAddress((void**)&pWB, g_WB);

    dim3 g(VOL / 256), b(256);

    k_init<<<1, 32>>>();

    // inverse-consistency: fwd = warp(warp(Ieps, AB), BA); bwd = warp(warp(Ieps, BA), AB)
    k_warp_ieps<<<g, b>>>(phiAB, noise);
    k_warp3_mse<<<g, b>>>(phiBA, noise);
    k_warp_ieps<<<g, b>>>(phiBA, noise);
    k_warp3_mse<<<g, b>>>(phiAB, noise);

    // similarity warps (materialized — needed by LNCC)
    k_warp1<<<g, b>>>(phiAB, imgA, pWA);
    k_warp1<<<g, b>>>(phiBA, imgB, pWB);

    // dice terms (fused warp + reductions)
    k_warp1_dice<<<g, b>>>(phiAB, labA, labB, 1);
    k_warp1_dice<<<g, b>>>(phiBA, labB, labA, 4);

    // lncc(warp(image_A, AB), image_B)
    k_blurZ<<<g, b>>>(pWA, imgB);
    k_blurY<<<g, b>>>();
    k_blurX_red<<<g, b>>>(7);

    // lncc(image_A, warp(image_B, BA))
    k_blurZ<<<g, b>>>(imgA, pWB);
    k_blurY<<<g, b>>>();
    k_blurX_red<<<g, b>>>(8);

    k_final<<<1, 1>>>(out);
}

// round 2
// speedup vs baseline: 1.1487x; 1.1487x over previous
#include <cuda_runtime.h>
#include <math.h>

#define DD  128
#define HW  16384            // 128*128
#define VOL 2097152          // 128^3
#define TY  16               // y-tile for fused blurYX

// ---- scratch (static device globals: allocation-free) ----
__device__ float4 g_ieps4[VOL];      // 32 MB: packed Ieps (z,y,x,pad)
__device__ float4 g_tmp4[VOL];       // 32 MB: intermediate 3-ch warped field
__device__ float2 g_A2[VOL];         // 16 MB: (imgA, labA)
__device__ float2 g_B2[VOL];         // 16 MB: (imgB, labB)
__device__ float  g_WA[VOL];         //  8 MB: warp(imgA, phiAB)
__device__ float  g_WB[VOL];         //  8 MB: warp(imgB, phiBA)
__device__ float  g_blur[10 * VOL];  // 80 MB: z-blurred 10 channels
__device__ double g_acc[16];

// gaussian kernel sigma=1 ksize=5
__constant__ float c_gk[5] = {
    0.05448868454964294f, 0.24420134200323332f, 0.40261995089424437f,
    0.24420134200323332f, 0.05448868454964294f };

__device__ __forceinline__ float idgv(int v) { return -1.0f + (float)v * (2.0f / 127.0f); }

__device__ __forceinline__ void get_coords(const float* __restrict__ phi, int i,
                                           float& z, float& y, float& x) {
    z = (phi[i]           + 1.0f) * 0.5f * 127.0f;
    y = (phi[VOL + i]     + 1.0f) * 0.5f * 127.0f;
    x = (phi[2 * VOL + i] + 1.0f) * 0.5f * 127.0f;
}

template <typename F>
__device__ __forceinline__ void tri_accum(float z, float y, float x, F f) {
    float zf = floorf(z), yf = floorf(y), xf = floorf(x);
    int z0 = (int)zf, y0 = (int)yf, x0 = (int)xf;
    float fz = z - zf, fy = y - yf, fx = x - xf;
    float wz0 = 1.0f - fz, wy0 = 1.0f - fy, wx0 = 1.0f - fx;
#pragma unroll
    for (int dz = 0; dz < 2; dz++) {
        int zi = z0 + dz;
        if (zi < 0 || zi >= DD) continue;
        float wz = dz ? fz : wz0;
#pragma unroll
        for (int dy = 0; dy < 2; dy++) {
            int yi = y0 + dy;
            if (yi < 0 || yi >= DD) continue;
            float wzy = wz * (dy ? fy : wy0);
#pragma unroll
            for (int dx = 0; dx < 2; dx++) {
                int xi = x0 + dx;
                if (xi < 0 || xi >= DD) continue;
                f((zi * DD + yi) * DD + xi, wzy * (dx ? fx : wx0));
            }
        }
    }
}

__device__ __forceinline__ void block_add(double v, double* dst) {
    __shared__ double sm[8];
    int lane = threadIdx.x & 31;
    int wid  = threadIdx.x >> 5;
#pragma unroll
    for (int o = 16; o > 0; o >>= 1) v += __shfl_down_sync(0xffffffffu, v, o);
    __syncthreads();
    if (lane == 0) sm[wid] = v;
    __syncthreads();
    if (wid == 0) {
        double t = (lane < 8) ? sm[lane] : 0.0;
#pragma unroll
        for (int o = 4; o > 0; o >>= 1) t += __shfl_down_sync(0xffffffffu, t, o);
        if (lane == 0) atomicAdd(dst, t);
    }
}

__global__ void k_init() {
    if (threadIdx.x < 16) g_acc[threadIdx.x] = 0.0;
}

// coalesced packing pre-pass: Ieps -> float4, (img,lab) -> float2
__global__ void k_pack(const float* __restrict__ noise,
                       const float* __restrict__ imgA, const float* __restrict__ labA,
                       const float* __restrict__ imgB, const float* __restrict__ labB) {
    int i = blockIdx.x * 256 + threadIdx.x;
    int zz = i >> 14, yy = (i >> 7) & 127, xx = i & 127;
    g_ieps4[i] = make_float4(idgv(zz) + noise[i]           * (1.0f / 128.0f),
                             idgv(yy) + noise[VOL + i]     * (1.0f / 128.0f),
                             idgv(xx) + noise[2 * VOL + i] * (1.0f / 128.0f), 0.0f);
    g_A2[i] = make_float2(imgA[i], labA[i]);
    g_B2[i] = make_float2(imgB[i], labB[i]);
}

// g_tmp4 = warp(Ieps, phi): one LDG.128 per corner
__global__ void k_warp_ieps4(const float* __restrict__ phi) {
    int i = blockIdx.x * 256 + threadIdx.x;
    float z, y, x;
    get_coords(phi, i, z, y, x);
    float o0 = 0.f, o1 = 0.f, o2 = 0.f;
    tri_accum(z, y, x, [&](int idx, float w) {
        float4 v = g_ieps4[idx];
        o0 += w * v.x; o1 += w * v.y; o2 += w * v.z;
    });
    g_tmp4[i] = make_float4(o0, o1, o2, 0.0f);
}

// acc[0] += sum((Ieps - warp(g_tmp4, phi))^2)
__global__ void k_warp3_mse4(const float* __restrict__ phi) {
    int i = blockIdx.x * 256 + threadIdx.x;
    float z, y, x;
    get_coords(phi, i, z, y, x);
    float o0 = 0.f, o1 = 0.f, o2 = 0.f;
    tri_accum(z, y, x, [&](int idx, float w) {
        float4 v = g_tmp4[idx];
        o0 += w * v.x; o1 += w * v.y; o2 += w * v.z;
    });
    float4 e = g_ieps4[i];
    float d0 = e.x - o0, d1 = e.y - o1, d2 = e.z - o2;
    block_add((double)(d0 * d0) + (double)(d1 * d1) + (double)(d2 * d2), &g_acc[0]);
}

// fused: warp image (store for LNCC) + warp label + dice partial sums
__global__ void k_warp_sim(const float* __restrict__ phi,
                           const float2* __restrict__ src2,   // (img, lab) to warp
                           const float2* __restrict__ oth2,   // .y = other label (linear)
                           float* __restrict__ wdst, int accbase) {
    int i = blockIdx.x * 256 + threadIdx.x;
    float z, y, x;
    get_coords(phi, i, z, y, x);
    float oi = 0.f, ol = 0.f;
    tri_accum(z, y, x, [&](int idx, float w) {
        float2 v = src2[idx];
        oi += w * v.x; ol += w * v.y;
    });
    wdst[i] = oi;
    float ov = oth2[i].y;
    block_add((double)(ol * ov), &g_acc[accbase]);
    block_add((double)ol,        &g_acc[accbase + 1]);
    block_add((double)ov,        &g_acc[accbase + 2]);
}

// z-blur of 10 channels for both LNCC pairs in one pass
__global__ void k_blurZ10(const float* __restrict__ imgA, const float* __restrict__ imgB) {
    int i = blockIdx.x * 256 + threadIdx.x;
    int z = i >> 14;
    float a[10];
#pragma unroll
    for (int c = 0; c < 10; c++) a[c] = 0.f;
#pragma unroll
    for (int t = 0; t < 5; t++) {
        int zz = z + t - 2;
        if ((unsigned)zz < (unsigned)DD) {
            int off = i + (t - 2) * HW;
            float k  = c_gk[t];
            float wa = g_WA[off], jb = imgB[off];
            float ia = imgA[off], wb = g_WB[off];
            a[0] += k * wa;      a[1] += k * jb;
            a[2] += k * wa * jb; a[3] += k * wa * wa; a[4] += k * jb * jb;
            a[5] += k * ia;      a[6] += k * wb;
            a[7] += k * ia * wb; a[8] += k * ia * ia; a[9] += k * wb * wb;
        }
    }
#pragma unroll
    for (int c = 0; c < 10; c++) g_blur[c * VOL + i] = a[c];
}

// fused y-blur + x-blur + LNCC reduction. block=256, tile = (1 z) x (TY y) x (128 x)
__global__ void k_blurYX_red() {
    extern __shared__ float sm[];
    float* sin_ = sm;              // 10ch x (TY+4) rows x 128 = 25600 floats
    float* srow = sm + 25600;      // 10ch x 2 rows x 128 = 2560 floats

    int tid = threadIdx.x;
    int z   = blockIdx.x >> 3;
    int y0  = (blockIdx.x & 7) * TY;

    // cooperative load with y halo (zeros outside -> matches zero-pad blur)
    for (int idx = tid; idx < 10 * (TY + 4) * 128; idx += 256) {
        int c   = idx / ((TY + 4) * 128);
        int rem = idx - c * (TY + 4) * 128;
        int r   = rem >> 7;
        int x   = rem & 127;
        int y   = y0 + r - 2;
        float v = 0.f;
        if ((unsigned)y < (unsigned)DD)
            v = g_blur[c * VOL + ((z << 7) + y) * DD + x];
        sin_[idx] = v;
    }
    __syncthreads();

    int half = tid >> 7;       // 0/1: which of 2 rows this iteration
    int x    = tid & 127;
    double local = 0.0;

#pragma unroll 1
    for (int it = 0; it < TY / 2; it++) {
        int ry = it * 2 + half;            // 0..TY-1 (center row index in tile)
        float val[10];
#pragma unroll
        for (int c = 0; c < 10; c++) val[c] = 0.f;
#pragma unroll
        for (int t = 0; t < 5; t++) {
            float k = c_gk[t];
            int r = ry + t;                // smem row (center at ry+2)
#pragma unroll
            for (int c = 0; c < 10; c++)
                val[c] += k * sin_[c * (TY + 4) * 128 + r * 128 + x];
        }
#pragma unroll
        for (int c = 0; c < 10; c++) srow[c * 256 + half * 128 + x] = val[c];
        __syncthreads();

        float v[10];
#pragma unroll
        for (int c = 0; c < 10; c++) v[c] = 0.f;
#pragma unroll
        for (int t = 0; t < 5; t++) {
            int xx = x + t - 2;
            if ((unsigned)xx < (unsigned)DD) {
                float k = c_gk[t];
#pragma unroll
                for (int c = 0; c < 10; c++)
                    v[c] += k * srow[c * 256 + half * 128 + xx];
            }
        }
        // LNCC terms for both pairs
        float cr1 = v[2] - v[0] * v[1];
        float vI1 = fmaxf(v[3] - v[0] * v[0], 0.f) + 1e-5f;
        float vJ1 = fmaxf(v[4] - v[1] * v[1], 0.f) + 1e-5f;
        float cr2 = v[7] - v[5] * v[6];
        float vI2 = fmaxf(v[8] - v[5] * v[5], 0.f) + 1e-5f;
        float vJ2 = fmaxf(v[9] - v[6] * v[6], 0.f) + 1e-5f;
        local += (double)(1.0f - cr1 * rsqrtf(vI1 * vJ1))
               + (double)(1.0f - cr2 * rsqrtf(vI2 * vJ2));
        __syncthreads();
    }
    block_add(local, &g_acc[7]);
}

__global__ void k_final(float* __restrict__ out) {
    double ic    = g_acc[0] / (3.0 * (double)VOL);
    double dice1 = (2.0 * g_acc[1] + 1e-5) / (g_acc[2] + g_acc[3] + 1e-5);
    double dice2 = (2.0 * g_acc[4] + 1e-5) / (g_acc[5] + g_acc[6] + 1e-5);
    double dl    = (1.0 - dice1) + (1.0 - dice2);
    double sim   = g_acc[7] / (double)VOL;
    out[0] = (float)(128.0 * ic + sim + dl);
}

extern "C" void kernel_launch(void* const* d_in, const int* in_sizes, int n_in,
                              void* d_out, int out_size) {
    const float* phiAB = (const float*)d_in[0];
    const float* phiBA = (const float*)d_in[1];
    const float* imgA  = (const float*)d_in[2];
    const float* imgB  = (const float*)d_in[3];
    const float* labA  = (const float*)d_in[4];
    const float* labB  = (const float*)d_in[5];
    const float* noise = (const float*)d_in[6];
    float* out = (float*)d_out;

    float  *pWA = nullptr, *pWB = nullptr;
    float2 *pA2 = nullptr, *pB2 = nullptr;
    cudaGetSymbolAddress((void**)&pWA, g_WA);
    cudaGetSymbolAddress((void**)&pWB, g_WB);
    cudaGetSymbolAddress((void**)&pA2, g_A2);
    cudaGetSymbolAddress((void**)&pB2, g_B2);

    const int smem_yx = (25600 + 2560) * sizeof(float);   // 112,640 B
    cudaFuncSetAttribute(k_blurYX_red,
                         cudaFuncAttributeMaxDynamicSharedMemorySize, smem_yx);

    dim3 g(VOL / 256), b(256);

    k_init<<<1, 32>>>();
    k_pack<<<g, b>>>(noise, imgA, labA, imgB, labB);

    // inverse consistency (fwd then bwd), fused final warp + MSE
    k_warp_ieps4<<<g, b>>>(phiAB);
    k_warp3_mse4<<<g, b>>>(phiBA);
    k_warp_ieps4<<<g, b>>>(phiBA);
    k_warp3_mse4<<<g, b>>>(phiAB);

    // similarity warps + dice (fused per direction)
    k_warp_sim<<<g, b>>>(phiAB, pA2, pB2, pWA, 1);
    k_warp_sim<<<g, b>>>(phiBA, pB2, pA2, pWB, 4);

    // both LNCC pairs: 10-channel z-blur, then fused y/x-blur + reduce
    k_blurZ10<<<g, b>>>(imgA, imgB);
    k_blurYX_red<<<1024, 256, smem_yx>>>();

    k_final<<<1, 1>>>(out);
}

// round 3
// speedup vs baseline: 1.3953x; 1.2147x over previous
#include <cuda_runtime.h>
#include <cuda_fp16.h>
#include <math.h>

#define DD  128
#define HW  16384            // 128*128
#define VOL 2097152          // 128^3
#define TY  16               // y-tile for fused blurYX

struct __align__(8) h4 { __half2 a; __half2 b; };

// ---- scratch (static device globals, allocation-free) ----
__device__ h4      g_noiseh[VOL];     // 16 MB: (nz,ny,nx,0) * 1/128, fp16
__device__ h4      g_tmpF[VOL];       // 16 MB: warp(Ieps, phi_AB)
__device__ h4      g_tmpB[VOL];       // 16 MB: warp(Ieps, phi_BA)
__device__ __half2 g_A2[VOL];         //  8 MB: (imgA, labA)
__device__ __half2 g_B2[VOL];         //  8 MB: (imgB, labB)
__device__ __half2 g_W2[VOL];         //  8 MB: (WA, WB)
__device__ __half  g_blur[10 * VOL];  // 40 MB: z-blurred 10 channels
__device__ double  g_acc[16];

// gaussian kernel sigma=1 ksize=5
__constant__ float c_gk[5] = {
    0.05448868454964294f, 0.24420134200323332f, 0.40261995089424437f,
    0.24420134200323332f, 0.05448868454964294f };

__device__ __forceinline__ float idgv(int v) { return -1.0f + (float)v * (2.0f / 127.0f); }

// per-axis trilinear prep: weights include validity; indices are clamped-safe
__device__ __forceinline__ void axis_prep(float c, float& w0, float& w1, int& i0, int& i1) {
    float f  = floorf(c);
    float fr = c - f;
    int j0 = (int)f;
    int j1 = j0 + 1;
    w0 = (j0 >= 0 && j0 < DD) ? (1.0f - fr) : 0.0f;
    w1 = (j1 >= 0 && j1 < DD) ? fr : 0.0f;
    i0 = min(max(j0, 0), DD - 1);
    i1 = min(max(j1, 0), DD - 1);
}

struct Axes {
    float wz[2], wy[2], wx[2];
    int   iz[2], iy[2], ix[2];
};

__device__ __forceinline__ Axes make_axes(const float* __restrict__ phi, int i) {
    Axes a;
    float z = (phi[i]           + 1.0f) * 63.5f;
    float y = (phi[VOL + i]     + 1.0f) * 63.5f;
    float x = (phi[2 * VOL + i] + 1.0f) * 63.5f;
    axis_prep(z, a.wz[0], a.wz[1], a.iz[0], a.iz[1]);
    axis_prep(y, a.wy[0], a.wy[1], a.iy[0], a.iy[1]);
    axis_prep(x, a.wx[0], a.wx[1], a.ix[0], a.ix[1]);
    return a;
}

// 8 unconditional straight-line half4 loads (3 channels used)
__device__ __forceinline__ float3 gather_h4(const h4* __restrict__ src, const Axes& a) {
    float acc0 = 0.f, acc1 = 0.f, acc2 = 0.f;
#pragma unroll
    for (int dz = 0; dz < 2; dz++) {
        int rz = a.iz[dz] * HW;
#pragma unroll
        for (int dy = 0; dy < 2; dy++) {
            int rzy = rz + a.iy[dy] * DD;
            float wzy = a.wz[dz] * a.wy[dy];
#pragma unroll
            for (int dx = 0; dx < 2; dx++) {
                float w = wzy * a.wx[dx];
                h4 v = src[rzy + a.ix[dx]];
                float2 p = __half22float2(v.a);
                float  q = __half2float(v.b.x);
                acc0 += w * p.x; acc1 += w * p.y; acc2 += w * q;
            }
        }
    }
    return make_float3(acc0, acc1, acc2);
}

// 8 unconditional half2 loads (2 channels)
__device__ __forceinline__ float2 gather_h2(const __half2* __restrict__ src, const Axes& a) {
    float acc0 = 0.f, acc1 = 0.f;
#pragma unroll
    for (int dz = 0; dz < 2; dz++) {
        int rz = a.iz[dz] * HW;
#pragma unroll
        for (int dy = 0; dy < 2; dy++) {
            int rzy = rz + a.iy[dy] * DD;
            float wzy = a.wz[dz] * a.wy[dy];
#pragma unroll
            for (int dx = 0; dx < 2; dx++) {
                float w = wzy * a.wx[dx];
                float2 p = __half22float2(src[rzy + a.ix[dx]]);
                acc0 += w * p.x; acc1 += w * p.y;
            }
        }
    }
    return make_float2(acc0, acc1);
}

// analytic warp(idg, phi): per-axis factorized sums -> 3 channels, zero loads
__device__ __forceinline__ float3 warp_idg(const Axes& a) {
    float Sz0 = a.wz[0] + a.wz[1];
    float Sy0 = a.wy[0] + a.wy[1];
    float Sx0 = a.wx[0] + a.wx[1];
    float Sz1 = a.wz[0] * idgv(a.iz[0]) + a.wz[1] * idgv(a.iz[1]);
    float Sy1 = a.wy[0] * idgv(a.iy[0]) + a.wy[1] * idgv(a.iy[1]);
    float Sx1 = a.wx[0] * idgv(a.ix[0]) + a.wx[1] * idgv(a.ix[1]);
    return make_float3(Sz1 * Sy0 * Sx0, Sz0 * Sy1 * Sx0, Sz0 * Sy0 * Sx1);
}

__device__ __forceinline__ void block_add(double v, double* dst) {
    __shared__ double sm[8];
    int lane = threadIdx.x & 31;
    int wid  = threadIdx.x >> 5;
#pragma unroll
    for (int o = 16; o > 0; o >>= 1) v += __shfl_down_sync(0xffffffffu, v, o);
    __syncthreads();
    if (lane == 0) sm[wid] = v;
    __syncthreads();
    if (wid == 0) {
        double t = (lane < 8) ? sm[lane] : 0.0;
#pragma unroll
        for (int o = 4; o > 0; o >>= 1) t += __shfl_down_sync(0xffffffffu, t, o);
        if (lane == 0) atomicAdd(dst, t);
    }
}

__global__ void k_init() {
    if (threadIdx.x < 16) g_acc[threadIdx.x] = 0.0;
}

// coalesced packing: noise/128 -> half4, (img,lab) -> half2
__global__ void k_pack(const float* __restrict__ noise,
                       const float* __restrict__ imgA, const float* __restrict__ labA,
                       const float* __restrict__ imgB, const float* __restrict__ labB) {
    int i = blockIdx.x * 256 + threadIdx.x;
    h4 h;
    h.a = __floats2half2_rn(noise[i] * (1.0f / 128.0f), noise[VOL + i] * (1.0f / 128.0f));
    h.b = __floats2half2_rn(noise[2 * VOL + i] * (1.0f / 128.0f), 0.0f);
    g_noiseh[i] = h;
    g_A2[i] = __floats2half2_rn(imgA[i], labA[i]);
    g_B2[i] = __floats2half2_rn(imgB[i], labB[i]);
}

// one pass over both phis: inner Ieps warps (both dirs) + sim/label warps + dice sums
__global__ void k_warp_all(const float* __restrict__ phiAB, const float* __restrict__ phiBA) {
    int i = blockIdx.x * 256 + threadIdx.x;
    Axes aAB = make_axes(phiAB, i);
    Axes aBA = make_axes(phiBA, i);

    // tmpF = warp(Ieps, AB) = warp(idg, AB) + warp(noise/128, AB)
    float3 gF = warp_idg(aAB);
    float3 nF = gather_h4(g_noiseh, aAB);
    float3 gB = warp_idg(aBA);
    float3 nB = gather_h4(g_noiseh, aBA);

    h4 oF, oB;
    oF.a = __floats2half2_rn(gF.x + nF.x, gF.y + nF.y);
    oF.b = __floats2half2_rn(gF.z + nF.z, 0.0f);
    oB.a = __floats2half2_rn(gB.x + nB.x, gB.y + nB.y);
    oB.b = __floats2half2_rn(gB.z + nB.z, 0.0f);
    g_tmpF[i] = oF;
    g_tmpB[i] = oB;

    // (WA, wlA) = warp((imgA, labA), AB) ; (WB, wlB) = warp((imgB, labB), BA)
    float2 wA = gather_h2(g_A2, aAB);
    float2 wB = gather_h2(g_B2, aBA);
    g_W2[i] = __floats2half2_rn(wA.x, wB.x);

    float lB = __half2float(__high2half(g_B2[i]));
    float lA = __half2float(__high2half(g_A2[i]));
    block_add((double)(wA.y * lB), &g_acc[1]);
    block_add((double)wA.y,        &g_acc[2]);
    block_add((double)lB,          &g_acc[3]);
    block_add((double)(wB.y * lA), &g_acc[4]);
    block_add((double)wB.y,        &g_acc[5]);
    block_add((double)lA,          &g_acc[6]);
}

// acc[0] += |Ieps - warp(tmpF, BA)|^2 + |Ieps - warp(tmpB, AB)|^2
__global__ void k_mse_both(const float* __restrict__ phiAB, const float* __restrict__ phiBA) {
    int i = blockIdx.x * 256 + threadIdx.x;
    Axes aBA = make_axes(phiBA, i);
    Axes aAB = make_axes(phiAB, i);
    float3 f = gather_h4(g_tmpF, aBA);
    float3 b = gather_h4(g_tmpB, aAB);

    h4 nh = g_noiseh[i];
    float2 n01 = __half22float2(nh.a);
    float  n2  = __half2float(nh.b.x);
    int zz = i >> 14, yy = (i >> 7) & 127, xx = i & 127;
    float e0 = idgv(zz) + n01.x;
    float e1 = idgv(yy) + n01.y;
    float e2 = idgv(xx) + n2;

    float d0 = e0 - f.x, d1 = e1 - f.y, d2 = e2 - f.z;
    float c0 = e0 - b.x, c1 = e1 - b.y, c2 = e2 - b.z;
    double s = (double)(d0 * d0) + (double)(d1 * d1) + (double)(d2 * d2)
             + (double)(c0 * c0) + (double)(c1 * c1) + (double)(c2 * c2);
    block_add(s, &g_acc[0]);
}

// z-blur of 10 channels {WA, B, WA*B, WA^2, B^2, A, WB, A*WB, A^2, WB^2}
__global__ void k_blurZ10(const float* __restrict__ imgA, const float* __restrict__ imgB) {
    int i = blockIdx.x * 256 + threadIdx.x;
    int z = i >> 14;
    float a[10];
#pragma unroll
    for (int c = 0; c < 10; c++) a[c] = 0.f;
#pragma unroll
    for (int t = 0; t < 5; t++) {
        int zz = z + t - 2;
        if ((unsigned)zz < (unsigned)DD) {
            int off = i + (t - 2) * HW;
            float k = c_gk[t];
            float2 w2 = __half22float2(g_W2[off]);
            float wa = w2.x, wb = w2.y;
            float ia = imgA[off], jb = imgB[off];
            a[0] += k * wa;      a[1] += k * jb;
            a[2] += k * wa * jb; a[3] += k * wa * wa; a[4] += k * jb * jb;
            a[5] += k * ia;      a[6] += k * wb;
            a[7] += k * ia * wb; a[8] += k * ia * ia; a[9] += k * wb * wb;
        }
    }
#pragma unroll
    for (int c = 0; c < 10; c++) g_blur[c * VOL + i] = __float2half_rn(a[c]);
}

// fused y-blur + x-blur + LNCC reduction. tile = (1 z) x (TY y) x (128 x)
__global__ void k_blurYX_red() {
    extern __shared__ char smraw[];
    __half* sin_ = (__half*)smraw;                    // 10ch x (TY+4) x 128 halfs = 51200 B
    float*  srow = (float*)(smraw + 10 * (TY + 4) * 128 * 2); // 10ch x 2 x 128 floats

    int tid = threadIdx.x;
    int z   = blockIdx.x >> 3;
    int y0  = (blockIdx.x & 7) * TY;

    // cooperative vectorized load (uint2 = 4 halfs) with y halo (zeros outside)
    uint2*       s4 = (uint2*)smraw;
    const uint2* gb = (const uint2*)&g_blur[0];
    const int units_per_ch = (TY + 4) * 32;           // 128 halfs/row / 4
    for (int u = tid; u < 10 * units_per_ch; u += 256) {
        int c   = u / units_per_ch;
        int rem = u - c * units_per_ch;
        int r   = rem >> 5;
        int xu  = rem & 31;
        int y   = y0 + r - 2;
        uint2 v = make_uint2(0u, 0u);
        if ((unsigned)y < (unsigned)DD)
            v = gb[((c * VOL + ((z << 7) + y) * DD) >> 2) + xu];
        s4[u] = v;
    }
    __syncthreads();

    int half_ = tid >> 7;    // which of 2 rows per iteration
    int x     = tid & 127;
    double local = 0.0;

#pragma unroll 1
    for (int it = 0; it < TY / 2; it++) {
        int ry = it * 2 + half_;
        float val[10];
#pragma unroll
        for (int c = 0; c < 10; c++) val[c] = 0.f;
#pragma unroll
        for (int t = 0; t < 5; t++) {
            float k = c_gk[t];
            int r = ry + t;
#pragma unroll
            for (int c = 0; c < 10; c++)
                val[c] += k * __half2float(sin_[c * (TY + 4) * 128 + r * 128 + x]);
        }
#pragma unroll
        for (int c = 0; c < 10; c++) srow[c * 256 + half_ * 128 + x] = val[c];
        __syncthreads();

        float v[10];
#pragma unroll
        for (int c = 0; c < 10; c++) v[c] = 0.f;
#pragma unroll
        for (int t = 0; t < 5; t++) {
            int xx = x + t - 2;
            if ((unsigned)xx < (unsigned)DD) {
                float k = c_gk[t];
#pragma unroll
                for (int c = 0; c < 10; c++)
                    v[c] += k * srow[c * 256 + half_ * 128 + xx];
            }
        }
        float cr1 = v[2] - v[0] * v[1];
        float vI1 = fmaxf(v[3] - v[0] * v[0], 0.f) + 1e-5f;
        float vJ1 = fmaxf(v[4] - v[1] * v[1], 0.f) + 1e-5f;
        float cr2 = v[7] - v[5] * v[6];
        float vI2 = fmaxf(v[8] - v[5] * v[5], 0.f) + 1e-5f;
        float vJ2 = fmaxf(v[9] - v[6] * v[6], 0.f) + 1e-5f;
        local += (double)(1.0f - cr1 * rsqrtf(vI1 * vJ1))
               + (double)(1.0f - cr2 * rsqrtf(vI2 * vJ2));
        __syncthreads();
    }
    block_add(local, &g_acc[7]);
}

__global__ void k_final(float* __restrict__ out) {
    double ic    = g_acc[0] / (3.0 * (double)VOL);
    double dice1 = (2.0 * g_acc[1] + 1e-5) / (g_acc[2] + g_acc[3] + 1e-5);
    double dice2 = (2.0 * g_acc[4] + 1e-5) / (g_acc[5] + g_acc[6] + 1e-5);
    double dl    = (1.0 - dice1) + (1.0 - dice2);
    double sim   = g_acc[7] / (double)VOL;
    out[0] = (float)(128.0 * ic + sim + dl);
}

extern "C" void kernel_launch(void* const* d_in, const int* in_sizes, int n_in,
                              void* d_out, int out_size) {
    const float* phiAB = (const float*)d_in[0];
    const float* phiBA = (const float*)d_in[1];
    const float* imgA  = (const float*)d_in[2];
    const float* imgB  = (const float*)d_in[3];
    const float* labA  = (const float*)d_in[4];
    const float* labB  = (const float*)d_in[5];
    const float* noise = (const float*)d_in[6];
    float* out = (float*)d_out;

    const int smem_yx = 10 * (TY + 4) * 128 * 2 + 10 * 2 * 128 * 4;  // 61,440 B
    cudaFuncSetAttribute(k_blurYX_red,
                         cudaFuncAttributeMaxDynamicSharedMemorySize, smem_yx);

    dim3 g(VOL / 256), b(256);

    k_init<<<1, 32>>>();
    k_pack<<<g, b>>>(noise, imgA, labA, imgB, labB);
    k_warp_all<<<g, b>>>(phiAB, phiBA);
    k_mse_both<<<g, b>>>(phiAB, phiBA);
    k_blurZ10<<<g, b>>>(imgA, imgB);
    k_blurYX_red<<<1024, 256, smem_yx>>>();
    k_final<<<1, 1>>>(out);
}

// round 4
// speedup vs baseline: 1.4676x; 1.0518x over previous
#include <cuda_runtime.h>
#include <cuda_fp16.h>
#include <math.h>

#define DD  128
#define HW  16384            // 128*128
#define VOL 2097152          // 128^3
#define TY  16               // y-tile for fused blurYX

// pair-of-h4: {v(x): z,y,x,pad | v(x+1): z,y,x,pad} -> one LDG.128 per x-pair
struct __align__(16) h4p { __half2 a, b, c, d; };
// pair-of-h2: {v(x) | v(x+1)} -> one LDG.64
struct __align__(8)  h2p { __half2 v0, v1; };

// ---- scratch (static device globals, allocation-free) ----
__device__ h4p     g_noisep[VOL];     // 32 MB: paired noise/128 (3ch)
__device__ h4p     g_tmpFp[VOL];      // 32 MB: paired warp(Ieps, AB)
__device__ h4p     g_tmpBp[VOL];      // 32 MB: paired warp(Ieps, BA)
__device__ h2p     g_A2p[VOL];        // 16 MB: paired (imgA, labA)
__device__ h2p     g_B2p[VOL];        // 16 MB: paired (imgB, labB)
__device__ __half2 g_W2[VOL];         //  8 MB: (WA, WB) linear
__device__ __half  g_blur[10 * VOL];  // 40 MB: z-blurred 10 channels
__device__ double  g_acc[16];

__constant__ float c_gk[5] = {
    0.05448868454964294f, 0.24420134200323332f, 0.40261995089424437f,
    0.24420134200323332f, 0.05448868454964294f };

__device__ __forceinline__ float idgv(int v) { return -1.0f + (float)v * (2.0f / 127.0f); }

// normal axis (z,y): validity-masked weights + clamped indices
__device__ __forceinline__ void axis_prep(float c, float& w0, float& w1, int& i0, int& i1) {
    float f  = floorf(c);
    float fr = c - f;
    int j0 = (int)f;
    w0 = (j0 >= 0 && j0 < DD)     ? (1.0f - fr) : 0.0f;
    w1 = (j0 >= -1 && j0 <= DD-2) ? fr          : 0.0f;
    i0 = min(max(j0, 0), DD - 1);
    i1 = min(max(j0 + 1, 0), DD - 1);
}

// x axis, pair-based: base element + weights mapped to pair slots
__device__ __forceinline__ void axis_prep_pair(float c, float& pw0, float& pw1, int& base) {
    float f  = floorf(c);
    float fr = c - f;
    int j0 = (int)f;
    float w0 = (j0 >= 0 && j0 < DD)     ? (1.0f - fr) : 0.0f;
    float w1 = (j0 >= -1 && j0 <= DD-2) ? fr          : 0.0f;
    if (j0 < 0) { pw0 = w1; pw1 = 0.0f; }   // pair[0] = {v0, v1}; corner x=0 -> slot 0
    else        { pw0 = w0; pw1 = w1;  }
    base = min(max(j0, 0), DD - 1);
}

struct Axes {
    float wz[2], wy[2];
    int   iz[2], iy[2];
    float pwx0, pwx1;
    int   ixb;
};

__device__ __forceinline__ Axes make_axes(const float* __restrict__ phi, int i) {
    Axes a;
    float z = (phi[i]           + 1.0f) * 63.5f;
    float y = (phi[VOL + i]     + 1.0f) * 63.5f;
    float x = (phi[2 * VOL + i] + 1.0f) * 63.5f;
    axis_prep(z, a.wz[0], a.wz[1], a.iz[0], a.iz[1]);
    axis_prep(y, a.wy[0], a.wy[1], a.iy[0], a.iy[1]);
    axis_prep_pair(x, a.pwx0, a.pwx1, a.ixb);
    return a;
}

// 4 unconditional LDG.128, 3 channels
__device__ __forceinline__ float3 gather_h4p(const h4p* __restrict__ src, const Axes& a) {
    float a0 = 0.f, a1 = 0.f, a2 = 0.f;
#pragma unroll
    for (int dz = 0; dz < 2; dz++) {
        int rz = a.iz[dz] * HW;
#pragma unroll
        for (int dy = 0; dy < 2; dy++) {
            float wzy = a.wz[dz] * a.wy[dy];
            float w0 = wzy * a.pwx0, w1 = wzy * a.pwx1;
            h4p v = src[rz + a.iy[dy] * DD + a.ixb];
            float2 p0 = __half22float2(v.a);
            float  q0 = __half2float(v.b.x);
            float2 p1 = __half22float2(v.c);
            float  q1 = __half2float(v.d.x);
            a0 += w0 * p0.x + w1 * p1.x;
            a1 += w0 * p0.y + w1 * p1.y;
            a2 += w0 * q0   + w1 * q1;
        }
    }
    return make_float3(a0, a1, a2);
}

// 4 unconditional LDG.64, 2 channels
__device__ __forceinline__ float2 gather_h2p(const h2p* __restrict__ src, const Axes& a) {
    float a0 = 0.f, a1 = 0.f;
#pragma unroll
    for (int dz = 0; dz < 2; dz++) {
        int rz = a.iz[dz] * HW;
#pragma unroll
        for (int dy = 0; dy < 2; dy++) {
            float wzy = a.wz[dz] * a.wy[dy];
            float w0 = wzy * a.pwx0, w1 = wzy * a.pwx1;
            h2p v = src[rz + a.iy[dy] * DD + a.ixb];
            float2 p0 = __half22float2(v.v0);
            float2 p1 = __half22float2(v.v1);
            a0 += w0 * p0.x + w1 * p1.x;
            a1 += w0 * p0.y + w1 * p1.y;
        }
    }
    return make_float2(a0, a1);
}

// analytic warp(idg, phi): zero loads
__device__ __forceinline__ float3 warp_idg(const Axes& a) {
    float Sz0 = a.wz[0] + a.wz[1];
    float Sy0 = a.wy[0] + a.wy[1];
    float Sx0 = a.pwx0 + a.pwx1;
    float Sz1 = a.wz[0] * idgv(a.iz[0]) + a.wz[1] * idgv(a.iz[1]);
    float Sy1 = a.wy[0] * idgv(a.iy[0]) + a.wy[1] * idgv(a.iy[1]);
    float Sx1 = a.pwx0 * idgv(a.ixb) + a.pwx1 * idgv(min(a.ixb + 1, DD - 1));
    return make_float3(Sz1 * Sy0 * Sx0, Sz0 * Sy1 * Sx0, Sz0 * Sy0 * Sx1);
}

__device__ __forceinline__ void block_add(double v, double* dst) {
    __shared__ double sm[8];
    int lane = threadIdx.x & 31;
    int wid  = threadIdx.x >> 5;
#pragma unroll
    for (int o = 16; o > 0; o >>= 1) v += __shfl_down_sync(0xffffffffu, v, o);
    __syncthreads();
    if (lane == 0) sm[wid] = v;
    __syncthreads();
    if (wid == 0) {
        double t = (lane < 8) ? sm[lane] : 0.0;
#pragma unroll
        for (int o = 4; o > 0; o >>= 1) t += __shfl_down_sync(0xffffffffu, t, o);
        if (lane == 0) atomicAdd(dst, t);
    }
}

__global__ void k_init() {
    if (threadIdx.x < 16) g_acc[threadIdx.x] = 0.0;
}

// coalesced packing into pair arrays (+ linear label sums for dice denominators)
__global__ void k_pack(const float* __restrict__ noise,
                       const float* __restrict__ imgA, const float* __restrict__ labA,
                       const float* __restrict__ imgB, const float* __restrict__ labB) {
    int i = blockIdx.x * 256 + threadIdx.x;
    int x = i & 127;
    int j = (x < 127) ? i + 1 : i;

    h4p n;
    n.a = __floats2half2_rn(noise[i] * (1.0f/128.0f), noise[VOL + i] * (1.0f/128.0f));
    n.b = __floats2half2_rn(noise[2*VOL + i] * (1.0f/128.0f), 0.0f);
    n.c = __floats2half2_rn(noise[j] * (1.0f/128.0f), noise[VOL + j] * (1.0f/128.0f));
    n.d = __floats2half2_rn(noise[2*VOL + j] * (1.0f/128.0f), 0.0f);
    g_noisep[i] = n;

    h2p pa, pb;
    float la = labA[i], lb = labB[i];
    pa.v0 = __floats2half2_rn(imgA[i], la);
    pa.v1 = __floats2half2_rn(imgA[j], labA[j]);
    pb.v0 = __floats2half2_rn(imgB[i], lb);
    pb.v1 = __floats2half2_rn(imgB[j], labB[j]);
    g_A2p[i] = pa;
    g_B2p[i] = pb;

    block_add((double)lb, &g_acc[3]);   // sum(label_B)
    block_add((double)la, &g_acc[6]);   // sum(label_A)
}

// both inner Ieps warps + both sim/label warps + dice numerators, one pass
__global__ void k_warp_all(const float* __restrict__ phiAB, const float* __restrict__ phiBA,
                           const float* __restrict__ labA, const float* __restrict__ labB) {
    __shared__ h4p smp[256];   // staging: voxel h4 values in .a/.b, rebuilt into pairs
    int tid = threadIdx.x;
    int i = blockIdx.x * 256 + tid;
    int x = tid & 127;
    int dn = (x < 127) ? 1 : 0;

    Axes aAB = make_axes(phiAB, i);
    Axes aBA = make_axes(phiBA, i);

    float3 gF = warp_idg(aAB);
    float3 nF = gather_h4p(g_noisep, aAB);
    float3 gB = warp_idg(aBA);
    float3 nB = gather_h4p(g_noisep, aBA);
    float2 wA = gather_h2p(g_A2p, aAB);
    float2 wB = gather_h2p(g_B2p, aBA);

    // stage F values, build pairs, write
    smp[tid].a = __floats2half2_rn(gF.x + nF.x, gF.y + nF.y);
    smp[tid].b = __floats2half2_rn(gF.z + nF.z, 0.0f);
    __syncthreads();
    { h4p o; o.a = smp[tid].a; o.b = smp[tid].b;
      o.c = smp[tid + dn].a; o.d = smp[tid + dn].b; g_tmpFp[i] = o; }
    __syncthreads();
    // stage B values, build pairs, write
    smp[tid].a = __floats2half2_rn(gB.x + nB.x, gB.y + nB.y);
    smp[tid].b = __floats2half2_rn(gB.z + nB.z, 0.0f);
    __syncthreads();
    { h4p o; o.a = smp[tid].a; o.b = smp[tid].b;
      o.c = smp[tid + dn].a; o.d = smp[tid + dn].b; g_tmpBp[i] = o; }

    g_W2[i] = __floats2half2_rn(wA.x, wB.x);

    block_add((double)(wA.y * labB[i]), &g_acc[1]);  // sum(wlA * labB)
    block_add((double)wA.y,             &g_acc[2]);  // sum(wlA)
    block_add((double)(wB.y * labA[i]), &g_acc[4]);  // sum(wlB * labA)
    block_add((double)wB.y,             &g_acc[5]);  // sum(wlB)
}

// acc[0] += |Ieps - warp(tmpF, BA)|^2 + |Ieps - warp(tmpB, AB)|^2
__global__ void k_mse_both(const float* __restrict__ phiAB, const float* __restrict__ phiBA) {
    int i = blockIdx.x * 256 + threadIdx.x;
    Axes aBA = make_axes(phiBA, i);
    Axes aAB = make_axes(phiAB, i);
    float3 f = gather_h4p(g_tmpFp, aBA);
    float3 b = gather_h4p(g_tmpBp, aAB);

    h4p nh = g_noisep[i];
    float2 n01 = __half22float2(nh.a);
    float  n2  = __half2float(nh.b.x);
    int zz = i >> 14, yy = (i >> 7) & 127, xx = i & 127;
    float e0 = idgv(zz) + n01.x;
    float e1 = idgv(yy) + n01.y;
    float e2 = idgv(xx) + n2;

    float d0 = e0 - f.x, d1 = e1 - f.y, d2 = e2 - f.z;
    float c0 = e0 - b.x, c1 = e1 - b.y, c2 = e2 - b.z;
    double s = (double)(d0*d0) + (double)(d1*d1) + (double)(d2*d2)
             + (double)(c0*c0) + (double)(c1*c1) + (double)(c2*c2);
    block_add(s, &g_acc[0]);
}

// z-blur of 10 channels {WA, B, WA*B, WA^2, B^2, A, WB, A*WB, A^2, WB^2}
__global__ void k_blurZ10(const float* __restrict__ imgA, const float* __restrict__ imgB) {
    int i = blockIdx.x * 256 + threadIdx.x;
    int z = i >> 14;
    float a[10];
#pragma unroll
    for (int c = 0; c < 10; c++) a[c] = 0.f;
#pragma unroll
    for (int t = 0; t < 5; t++) {
        int zz = z + t - 2;
        if ((unsigned)zz < (unsigned)DD) {
            int off = i + (t - 2) * HW;
            float k = c_gk[t];
            float2 w2 = __half22float2(g_W2[off]);
            float wa = w2.x, wb = w2.y;
            float ia = imgA[off], jb = imgB[off];
            a[0] += k * wa;      a[1] += k * jb;
            a[2] += k * wa * jb; a[3] += k * wa * wa; a[4] += k * jb * jb;
            a[5] += k * ia;      a[6] += k * wb;
            a[7] += k * ia * wb; a[8] += k * ia * ia; a[9] += k * wb * wb;
        }
    }
#pragma unroll
    for (int c = 0; c < 10; c++) g_blur[c * VOL + i] = __float2half_rn(a[c]);
}

// fused y-blur + x-blur + LNCC reduction. tile = (1 z) x (TY y) x (128 x)
__global__ void k_blurYX_red() {
    extern __shared__ char smraw[];
    __half* sin_ = (__half*)smraw;                              // 10*(TY+4)*128 halfs
    float*  srow = (float*)(smraw + 10 * (TY + 4) * 128 * 2);   // 10*2*128 floats

    int tid = threadIdx.x;
    int z   = blockIdx.x >> 3;
    int y0  = (blockIdx.x & 7) * TY;

    uint2*       s4 = (uint2*)smraw;
    const uint2* gb = (const uint2*)&g_blur[0];
    const int units_per_ch = (TY + 4) * 32;
    for (int u = tid; u < 10 * units_per_ch; u += 256) {
        int c   = u / units_per_ch;
        int rem = u - c * units_per_ch;
        int r   = rem >> 5;
        int xu  = rem & 31;
        int y   = y0 + r - 2;
        uint2 v = make_uint2(0u, 0u);
        if ((unsigned)y < (unsigned)DD)
            v = gb[((c * VOL + ((z << 7) + y) * DD) >> 2) + xu];
        s4[u] = v;
    }
    __syncthreads();

    int half_ = tid >> 7;
    int x     = tid & 127;
    double local = 0.0;

#pragma unroll 1
    for (int it = 0; it < TY / 2; it++) {
        int ry = it * 2 + half_;
        float val[10];
#pragma unroll
        for (int c = 0; c < 10; c++) val[c] = 0.f;
#pragma unroll
        for (int t = 0; t < 5; t++) {
            float k = c_gk[t];
            int r = ry + t;
#pragma unroll
            for (int c = 0; c < 10; c++)
                val[c] += k * __half2float(sin_[c * (TY + 4) * 128 + r * 128 + x]);
        }
#pragma unroll
        for (int c = 0; c < 10; c++) srow[c * 256 + half_ * 128 + x] = val[c];
        __syncthreads();

        float v[10];
#pragma unroll
        for (int c = 0; c < 10; c++) v[c] = 0.f;
#pragma unroll
        for (int t = 0; t < 5; t++) {
            int xx = x + t - 2;
            if ((unsigned)xx < (unsigned)DD) {
                float k = c_gk[t];
#pragma unroll
                for (int c = 0; c < 10; c++)
                    v[c] += k * srow[c * 256 + half_ * 128 + xx];
            }
        }
        float cr1 = v[2] - v[0] * v[1];
        float vI1 = fmaxf(v[3] - v[0] * v[0], 0.f) + 1e-5f;
        float vJ1 = fmaxf(v[4] - v[1] * v[1], 0.f) + 1e-5f;
        float cr2 = v[7] - v[5] * v[6];
        float vI2 = fmaxf(v[8] - v[5] * v[5], 0.f) + 1e-5f;
        float vJ2 = fmaxf(v[9] - v[6] * v[6], 0.f) + 1e-5f;
        local += (double)(1.0f - cr1 * rsqrtf(vI1 * vJ1))
               + (double)(1.0f - cr2 * rsqrtf(vI2 * vJ2));
        __syncthreads();
    }
    block_add(local, &g_acc[7]);
}

__global__ void k_final(float* __restrict__ out) {
    double ic    = g_acc[0] / (3.0 * (double)VOL);
    double dice1 = (2.0 * g_acc[1] + 1e-5) / (g_acc[2] + g_acc[3] + 1e-5);
    double dice2 = (2.0 * g_acc[4] + 1e-5) / (g_acc[5] + g_acc[6] + 1e-5);
    double dl    = (1.0 - dice1) + (1.0 - dice2);
    double sim   = g_acc[7] / (double)VOL;
    out[0] = (float)(128.0 * ic + sim + dl);
}

extern "C" void kernel_launch(void* const* d_in, const int* in_sizes, int n_in,
                              void* d_out, int out_size) {
    const float* phiAB = (const float*)d_in[0];
    const float* phiBA = (const float*)d_in[1];
    const float* imgA  = (const float*)d_in[2];
    const float* imgB  = (const float*)d_in[3];
    const float* labA  = (const float*)d_in[4];
    const float* labB  = (const float*)d_in[5];
    const float* noise = (const float*)d_in[6];
    float* out = (float*)d_out;

    const int smem_yx = 10 * (TY + 4) * 128 * 2 + 10 * 2 * 128 * 4;  // 61,440 B
    cudaFuncSetAttribute(k_blurYX_red,
                         cudaFuncAttributeMaxDynamicSharedMemorySize, smem_yx);

    dim3 g(VOL / 256), b(256);

    k_init<<<1, 32>>>();
    k_pack<<<g, b>>>(noise, imgA, labA, imgB, labB);
    k_warp_all<<<g, b>>>(phiAB, phiBA, labA, labB);
    k_mse_both<<<g, b>>>(phiAB, phiBA);
    k_blurZ10<<<g, b>>>(imgA, imgB);
    k_blurYX_red<<<1024, 256, smem_yx>>>();
    k_final<<<1, 1>>>(out);
}